// round 16
// baseline (speedup 1.0000x reference)
#include <cuda_runtime.h>
#include <math.h>
#include <float.h>

// Shapes: x (64, 33, 16, 16) f32. FM=16, CIN=32, DIM=256, HEADS=8, hd=32.

__device__ float g_morph[64 * 4 * 16 * 256];  // [b][map][o][pos]
__device__ float g_xn[64 * 33 * 256];         // LN'd tokens (row0 from qcls, rows1..32 from conv)
__device__ float g_r[64 * 8 * 256];           // per-(b,h) projected query row
__device__ float g_wpack[2 * 576 * 16];       // conv weights, [br][k][o], bn folded
__device__ float g_cbias[2 * 16];             // folded bias
__device__ float g_wmT[4 * 288 * 16];         // morph weights transposed [map][cij][o]
__device__ float g_delta[1];                  // prune threshold width

// ---- f32x2 helpers ----
__device__ __forceinline__ unsigned long long f2fma(unsigned long long a, unsigned long long b,
                                                    unsigned long long c) {
    unsigned long long d;
    asm("fma.rn.f32x2 %0, %1, %2, %3;" : "=l"(d) : "l"(a), "l"(b), "l"(c));
    return d;
}
__device__ __forceinline__ unsigned long long f2dup(float x) {
    unsigned long long d;
    unsigned int u = __float_as_uint(x);
    asm("mov.b64 %0, {%1, %2};" : "=l"(d) : "r"(u), "r"(u));
    return d;
}
__device__ __forceinline__ void f2unpack(unsigned long long v, float& lo, float& hi) {
    unsigned int a, b;
    asm("mov.b64 {%0, %1}, %2;" : "=r"(a), "=r"(b) : "l"(v));
    lo = __uint_as_float(a); hi = __uint_as_float(b);
}

// ---------------------------------------------------------------------------
// Prep: morph transpose + delta + conv pack. grid 11, 256 thr.
// ---------------------------------------------------------------------------
__global__ void k_prep(const float* __restrict__ w_se, const float* __restrict__ w_sd,
                       const float* __restrict__ w_te, const float* __restrict__ w_td,
    const float* __restrict__ s_c1w, const float* __restrict__ s_c1b,
    const float* __restrict__ s_c2w, const float* __restrict__ s_c2b,
    const float* __restrict__ s_g, const float* __restrict__ s_b,
    const float* __restrict__ s_m, const float* __restrict__ s_v,
    const float* __restrict__ t_c1w, const float* __restrict__ t_c1b,
    const float* __restrict__ t_c2w, const float* __restrict__ t_c2b,
    const float* __restrict__ t_g, const float* __restrict__ t_b,
    const float* __restrict__ t_m, const float* __restrict__ t_v)
{
    const int tid = threadIdx.x;
    const int bid = blockIdx.x;
    const float* wsrc[4] = {w_se, w_sd, w_te, w_td};

    if (bid < 8) {
        int m = bid >> 1, half = bid & 1;
        const float* src = wsrc[m];
        for (int e = half * 2304 + tid; e < half * 2304 + 2304; e += 256) {
            int cij = e >> 4, o = e & 15;
            g_wmT[m * 4608 + e] = src[o * 288 + cij];
        }
    } else if (bid == 8) {
        __shared__ float red[16];
        float mx = -FLT_MAX, mn = FLT_MAX;
        for (int i = tid; i < 18432; i += 256) {
            float v = wsrc[i / 4608][i % 4608];
            mx = fmaxf(mx, v); mn = fminf(mn, v);
        }
        for (int off = 16; off > 0; off >>= 1) {
            mx = fmaxf(mx, __shfl_xor_sync(0xffffffffu, mx, off));
            mn = fminf(mn, __shfl_xor_sync(0xffffffffu, mn, off));
        }
        int wid = tid >> 5, lane = tid & 31;
        if (lane == 0) { red[wid] = mx; red[8 + wid] = mn; }
        __syncthreads();
        if (tid == 0) {
            float a = red[0], c = red[8];
            for (int i = 1; i < 8; i++) { a = fmaxf(a, red[i]); c = fminf(c, red[8 + i]); }
            g_delta[0] = (a - c) * 1.0001f + 1e-6f;
        }
    } else if (bid == 9) {
        for (int i = tid; i < 512; i += 256) {
            int k = i >> 4, o = i & 15;
            int ch = k >> 1, m = k & 1;
            float bns = s_g[o] * rsqrtf(s_v[o] + 1e-5f);
            float w = (m ? s_c2w : s_c1w)[o * 16 + ch];
            g_wpack[k * 16 + o] = w * bns;
        }
        if (tid < 16) {
            float bns = s_g[tid] * rsqrtf(s_v[tid] + 1e-5f);
            g_cbias[tid] = (s_c1b[tid] + s_c2b[tid]) * bns + s_b[tid] - s_m[tid] * bns;
        }
    } else {
        for (int i = tid; i < 9216; i += 256) {
            int k = i >> 4, o = i & 15;
            int ch = k / 18; int r = k % 18; int m = r / 9; int tap = r % 9;
            float bns = t_g[o] * rsqrtf(t_v[o] + 1e-5f);
            float w = (m ? t_c2w : t_c1w)[(o * 16 + ch) * 9 + tap];
            g_wpack[9216 + k * 16 + o] = w * bns;
        }
        if (tid < 16) {
            float bns = t_g[tid] * rsqrtf(t_v[tid] + 1e-5f);
            g_cbias[16 + tid] = (t_c1b[tid] + t_c2b[tid]) * bns + t_b[tid] - t_m[tid] * bns;
        }
    }
}

// ---------------------------------------------------------------------------
// qcls: cls-LN + q_h + r_h per (head, batch). grid (8, 64), 128 threads.
// ---------------------------------------------------------------------------
__global__ void k_qcls(const float* __restrict__ x,
                       const float* __restrict__ wq, const float* __restrict__ wk,
                       const float* __restrict__ an_g, const float* __restrict__ an_b)
{
    __shared__ float xn0[256];
    __shared__ float qs[32];
    __shared__ float red[10];

    const int tid = threadIdx.x;
    const int h   = blockIdx.x;
    const int b   = blockIdx.y;
    const int wid = tid >> 5, lane = tid & 31;

    float v0 = x[b * 33 * 256 + tid];
    float v1 = x[b * 33 * 256 + tid + 128];
    {
        float s = v0 + v1, sq = v0 * v0 + v1 * v1;
        #pragma unroll
        for (int off = 16; off > 0; off >>= 1) {
            s  += __shfl_xor_sync(0xffffffffu, s, off);
            sq += __shfl_xor_sync(0xffffffffu, sq, off);
        }
        if (lane == 0) { red[wid] = s; red[4 + wid] = sq; }
        __syncthreads();
        if (tid == 0) {
            float ts = red[0] + red[1] + red[2] + red[3];
            float tq = red[4] + red[5] + red[6] + red[7];
            float mu = ts * (1.f / 256.f);
            red[8] = mu;
            red[9] = rsqrtf(tq * (1.f / 256.f) - mu * mu + 1e-6f);
        }
        __syncthreads();
        float mu = red[8], inv = red[9];
        float a0 = (v0 - mu) * inv * an_g[tid] + an_b[tid];
        float a1 = (v1 - mu) * inv * an_g[tid + 128] + an_b[tid + 128];
        xn0[tid] = a0; xn0[tid + 128] = a1;
        if (h == 0) {
            g_xn[b * 33 * 256 + tid] = a0;
            g_xn[b * 33 * 256 + tid + 128] = a1;
        }
    }
    __syncthreads();
    {
        int d = tid >> 2, part = tid & 3;
        const float4* wr = (const float4*)(wq + (h * 32 + d) * 256 + part * 64);
        const float4* x0 = (const float4*)(xn0 + part * 64);
        float acc = 0.f;
        #pragma unroll
        for (int e = 0; e < 16; e++) {
            float4 a = wr[e], c = x0[e];
            acc += a.x * c.x + a.y * c.y + a.z * c.z + a.w * c.w;
        }
        acc += __shfl_xor_sync(0xffffffffu, acc, 1);
        acc += __shfl_xor_sync(0xffffffffu, acc, 2);
        if (part == 0) qs[d] = acc;
    }
    __syncthreads();
    {
        float a0 = 0.f, a1 = 0.f;
        const float* wkb = wk + (h * 32) * 256;
        #pragma unroll 8
        for (int d = 0; d < 32; d++) {
            float qv = qs[d];
            a0 += qv * wkb[d * 256 + tid];
            a1 += qv * wkb[d * 256 + tid + 128];
        }
        g_r[(b * 8 + h) * 256 + tid] = a0;
        g_r[(b * 8 + h) * 256 + tid + 128] = a1;
    }
}

// smem float offsets for k_morph v5 (warp-uniform)
#define M5_XS  0        // 32*324 = 10368 (padded 18x18 per channel)
#define M5_W   10368    // 4608 (this map's [cij][16o])
#define M5_HM  14976    // 32*288 = 9216 (18 rows x 16 centers)
#define M5_TH  24192    // 256 thresholds
#define M5_MK  24448    // 256 masks (as uint in float slot)
#define M5_TOT 24704    // 98816 B

// ---------------------------------------------------------------------------
// Morphology v5: warp-uniform candidates. grid (4 maps, 64 b), 256 threads.
// Half-warp = 16 o-channels of ONE position -> uniform masks, LDS-only hits.
// ---------------------------------------------------------------------------
__global__ void __launch_bounds__(256, 2)
k_morph(const float* __restrict__ x)
{
    extern __shared__ float sm[];
    float* xs  = sm + M5_XS;
    float* wsm = sm + M5_W;
    float* hm  = sm + M5_HM;
    float* thr = sm + M5_TH;
    unsigned* msk = (unsigned*)(sm + M5_MK);

    const int tid = threadIdx.x;     // 0..255
    const int map = blockIdx.x;      // 0 spec_ero,1 spec_dil,2 spat_ero,3 spat_dil
    const int b   = blockIdx.y;
    const bool dil = (map == 1) || (map == 3);

    // stage x (padded 18x18 per channel) — predicated
    for (int i = tid; i < 10368; i += 256) {
        int c = i / 324; int rem = i - c * 324;
        int pr = rem / 18, pc = rem % 18;
        int gr = pr - 1, gc = pc - 1;
        float v = 0.f;
        if (gr >= 0 && gr < 16 && gc >= 0 && gc < 16)
            v = x[((b * 33 + 1 + c) * 16 + gr) * 16 + gc];
        xs[i] = v;
    }
    // stage this map's transposed weights (float4)
    {
        const float4* src = (const float4*)(g_wmT + map * 4608);
        for (int i = tid; i < 1152; i += 256) ((float4*)wsm)[i] = src[i];
    }
    __syncthreads();
    // horizontal 3-tap extrema: hm[c*288 + r*16 + w], r = 0..17 padded rows
    if (dil) {
        for (int i = tid; i < 9216; i += 256) {
            int c = i / 288; int rem = i - c * 288;
            int base = c * 324 + (rem >> 4) * 18 + (rem & 15);
            hm[i] = fmaxf(fmaxf(xs[base], xs[base + 1]), xs[base + 2]);
        }
    } else {
        for (int i = tid; i < 9216; i += 256) {
            int c = i / 288; int rem = i - c * 288;
            int base = c * 324 + (rem >> 4) * 18 + (rem & 15);
            hm[i] = fminf(fminf(xs[base], xs[base + 1]), xs[base + 2]);
        }
    }
    __syncthreads();
    // per-position threshold + candidate mask (one thread per position)
    {
        const float delta = g_delta[0];
        int lh = tid >> 4, lw = tid & 15;
        const float* hb = hm + lh * 16 + lw;
        float ext = dil ? -FLT_MAX : FLT_MAX;
        if (dil) {
            #pragma unroll 8
            for (int c = 0; c < 32; c++) {
                const float* p = hb + c * 288;
                ext = fmaxf(ext, fmaxf(fmaxf(p[0], p[16]), p[32]));
            }
        } else {
            #pragma unroll 8
            for (int c = 0; c < 32; c++) {
                const float* p = hb + c * 288;
                ext = fminf(ext, fminf(fminf(p[0], p[16]), p[32]));
            }
        }
        float th = dil ? (ext - delta) : (ext + delta);
        unsigned m = 0;
        if (dil) {
            #pragma unroll 8
            for (int c = 0; c < 32; c++) {
                const float* p = hb + c * 288;
                float pe = fmaxf(fmaxf(p[0], p[16]), p[32]);
                m |= (pe >= th ? 1u : 0u) << c;
            }
        } else {
            #pragma unroll 8
            for (int c = 0; c < 32; c++) {
                const float* p = hb + c * 288;
                float pe = fminf(fminf(p[0], p[16]), p[32]);
                m |= (pe <= th ? 1u : 0u) << c;
            }
        }
        thr[tid] = th;
        msk[tid] = m;
    }
    __syncthreads();

    // output: warp w owns positions [w*32, w*32+32); 16 passes of 2 positions.
    const int w    = tid >> 5;
    const int lane = tid & 31;
    const int o    = lane & 15;       // output channel within pass
    const int hsel = lane >> 4;       // half-warp -> position select
    const float sgn = dil ? 1.f : -1.f;
    float* gb = g_morph + b * 16384 + map * 4096;

    for (int pass = 0; pass < 16; pass++) {
        int pos = w * 32 + pass * 2 + hsel;
        int lh = pos >> 4, lw = pos & 15;
        float th = thr[pos];
        unsigned m = msk[pos];
        float acc = -FLT_MAX;
        while (m) {
            int c = __ffs(m) - 1; m &= m - 1;
            const float* xb = xs + c * 324 + lh * 18 + lw;
            const float* wc = wsm + c * 144 + o;     // (c*9+tap)*16 + o
            #pragma unroll
            for (int tap = 0; tap < 9; tap++) {
                int ir = tap / 3, jc = tap % 3;
                float v = xb[ir * 18 + jc];
                bool hit = dil ? (v >= th) : (v <= th);
                if (hit) {
                    float s = dil ? v : -v;
                    acc = fmaxf(acc, wc[tap * 16] + s);
                }
            }
        }
        gb[o * 256 + pos] = sgn * acc;
    }
}

// ---------------------------------------------------------------------------
// Conv (R14 config, measured 25.1us): grid (2, 64), 512 threads, fused an-LN.
// ---------------------------------------------------------------------------
__global__ void k_conv(const float* __restrict__ an_g, const float* __restrict__ an_b,
                       float* __restrict__ out)
{
    extern __shared__ float cs[];
    float* wsm = cs;              // 9216
    float* dsm = cs + 9216;       // 11520
    float* cbs = cs + 20736;      // 16
    __shared__ float psum[16][4], psq[16][4];
    __shared__ float mv[16][2];

    const int tid = threadIdx.x;
    const int br  = blockIdx.x;
    const int b   = blockIdx.y;

    {
        const float4* ws4 = (const float4*)(g_wpack + br * 9216);
        const int n4 = br ? 2304 : 128;
        for (int i = tid; i < n4; i += 512) ((float4*)wsm)[i] = ws4[i];
    }
    if (tid < 16) cbs[tid] = g_cbias[br * 16 + tid];
    for (int i = tid; i < 2880; i += 512) ((float4*)dsm)[i] = make_float4(0.f, 0.f, 0.f, 0.f);
    __syncthreads();
    {
        const float* gm = g_morph + (b * 4 + br * 2) * 4096;
        for (int i = tid; i < 8192; i += 512) {
            int m = i >> 12; int ch = (i >> 8) & 15; int p = i & 255;
            int h = p >> 4; int w = p & 15;
            dsm[(m * 16 + ch) * 360 + (h + 1) * 20 + (w + 1)] = gm[i];
        }
    }
    __syncthreads();

    const int osel4 = tid >> 7;
    const int ob0   = osel4 * 4;
    const int p2    = tid & 127;
    const int h     = p2 >> 3;
    const int w0    = (p2 & 7) * 2;

    unsigned long long acc0[2], acc1[2];
    {
        const unsigned long long* cbp = (const unsigned long long*)(cbs + ob0);
        acc0[0] = cbp[0]; acc0[1] = cbp[1];
        acc1[0] = cbp[0]; acc1[1] = cbp[1];
    }

    if (br == 0) {
        #pragma unroll 8
        for (int k = 0; k < 32; k++) {
            int ch = k >> 1, m = k & 1;
            const float* db = dsm + (m * 16 + ch) * 360 + (h + 1) * 20 + (w0 + 1);
            unsigned long long d0 = f2dup(db[0]);
            unsigned long long d1 = f2dup(db[1]);
            float4 w4 = *(const float4*)(wsm + k * 16 + ob0);
            unsigned long long wlo, whi;
            {
                unsigned int ax = __float_as_uint(w4.x), ay = __float_as_uint(w4.y);
                unsigned int az = __float_as_uint(w4.z), aw = __float_as_uint(w4.w);
                asm("mov.b64 %0, {%1, %2};" : "=l"(wlo) : "r"(ax), "r"(ay));
                asm("mov.b64 %0, {%1, %2};" : "=l"(whi) : "r"(az), "r"(aw));
            }
            acc0[0] = f2fma(wlo, d0, acc0[0]);
            acc0[1] = f2fma(whi, d0, acc0[1]);
            acc1[0] = f2fma(wlo, d1, acc1[0]);
            acc1[1] = f2fma(whi, d1, acc1[1]);
        }
    } else {
        #pragma unroll 1
        for (int ch = 0; ch < 16; ch++) {
            #pragma unroll
            for (int m = 0; m < 2; m++) {
                const float* db = dsm + (m * 16 + ch) * 360 + h * 20 + w0;
                float r0[4], r1[4], r2[4];
                {
                    float2 t;
                    t = *(const float2*)(db);          r0[0] = t.x; r0[1] = t.y;
                    t = *(const float2*)(db + 2);      r0[2] = t.x; r0[3] = t.y;
                    t = *(const float2*)(db + 20);     r1[0] = t.x; r1[1] = t.y;
                    t = *(const float2*)(db + 22);     r1[2] = t.x; r1[3] = t.y;
                    t = *(const float2*)(db + 40);     r2[0] = t.x; r2[1] = t.y;
                    t = *(const float2*)(db + 42);     r2[2] = t.x; r2[3] = t.y;
                }
                const float* wb = wsm + (ch * 18 + m * 9) * 16 + ob0;
                #pragma unroll
                for (int tap = 0; tap < 9; tap++) {
                    int ki = tap / 3, kj = tap % 3;
                    float va, vb2;
                    if (ki == 0)      { va = r0[kj]; vb2 = r0[kj + 1]; }
                    else if (ki == 1) { va = r1[kj]; vb2 = r1[kj + 1]; }
                    else              { va = r2[kj]; vb2 = r2[kj + 1]; }
                    unsigned long long d0 = f2dup(va);
                    unsigned long long d1 = f2dup(vb2);
                    float4 w4 = *(const float4*)(wb + tap * 16);
                    unsigned long long wlo, whi;
                    {
                        unsigned int ax = __float_as_uint(w4.x), ay = __float_as_uint(w4.y);
                        unsigned int az = __float_as_uint(w4.z), aw = __float_as_uint(w4.w);
                        asm("mov.b64 %0, {%1, %2};" : "=l"(wlo) : "r"(ax), "r"(ay));
                        asm("mov.b64 %0, {%1, %2};" : "=l"(whi) : "r"(az), "r"(aw));
                    }
                    acc0[0] = f2fma(wlo, d0, acc0[0]);
                    acc0[1] = f2fma(whi, d0, acc0[1]);
                    acc1[0] = f2fma(wlo, d1, acc1[0]);
                    acc1[1] = f2fma(whi, d1, acc1[1]);
                }
            }
        }
    }

    float z0[4], z1[4];
    f2unpack(acc0[0], z0[0], z0[1]);
    f2unpack(acc0[1], z0[2], z0[3]);
    f2unpack(acc1[0], z1[0], z1[1]);
    f2unpack(acc1[1], z1[2], z1[3]);

    const int pos0 = h * 16 + w0;
    const int wg   = (tid >> 5) & 3;
    const int lane = tid & 31;
    float* ob = out + (b * 33 + 1 + br * 16 + ob0) * 256;
    float g0[4], g1[4];
    #pragma unroll
    for (int ol = 0; ol < 4; ol++) {
        float a = z0[ol], c = z1[ol];
        float ga = 0.5f * a * (1.f + erff(a * 0.70710678118654752f));
        float gc = 0.5f * c * (1.f + erff(c * 0.70710678118654752f));
        g0[ol] = ga; g1[ol] = gc;
        *(float2*)(ob + ol * 256 + pos0) = make_float2(ga, gc);
        float s = ga + gc, sq = ga * ga + gc * gc;
        #pragma unroll
        for (int off = 16; off > 0; off >>= 1) {
            s  += __shfl_xor_sync(0xffffffffu, s, off);
            sq += __shfl_xor_sync(0xffffffffu, sq, off);
        }
        if (lane == 0) { psum[ob0 + ol][wg] = s; psq[ob0 + ol][wg] = sq; }
    }
    __syncthreads();
    if (tid < 16) {
        float s = psum[tid][0] + psum[tid][1] + psum[tid][2] + psum[tid][3];
        float sq = psq[tid][0] + psq[tid][1] + psq[tid][2] + psq[tid][3];
        float mu = s * (1.f / 256.f);
        float var = sq * (1.f / 256.f) - mu * mu;
        mv[tid][0] = mu;
        mv[tid][1] = rsqrtf(var + 1e-6f);
    }
    __syncthreads();
    float2 ag = *(const float2*)(an_g + pos0);
    float2 ab = *(const float2*)(an_b + pos0);
    float* xb = g_xn + (b * 33 + 1 + br * 16 + ob0) * 256;
    #pragma unroll
    for (int ol = 0; ol < 4; ol++) {
        float mu = mv[ob0 + ol][0], inv = mv[ob0 + ol][1];
        *(float2*)(xb + ol * 256 + pos0) =
            make_float2((g0[ol] - mu) * inv * ag.x + ab.x,
                        (g1[ol] - mu) * inv * ag.y + ab.y);
    }
}

// smem float offsets for k_tail
#define TO_XS  0        // 33*260 = 8580
#define TO_RR  8580     // 2048
#define TO_SS  10628    // 272
#define TO_UU  10900    // 2048
#define TO_OO  12948    // 256
#define TO_CLS 13204    // 256
#define TO_RED 13460    // 32
#define TO_TOT 13492

// ---------------------------------------------------------------------------
// Tail: scores..cn-LN. grid 64, 512 threads. (R14 config)
// ---------------------------------------------------------------------------
__global__ void k_tail(const float* __restrict__ x,
                       const float* __restrict__ wv,
                       const float* __restrict__ pw, const float* __restrict__ pb,
                       const float* __restrict__ cng, const float* __restrict__ cnb,
                       float* __restrict__ out)
{
    extern __shared__ float ts[];
    float* xs  = ts + TO_XS;
    float* rr  = ts + TO_RR;
    float* ss  = ts + TO_SS;
    float* uu  = ts + TO_UU;
    float* oo  = ts + TO_OO;
    float* cls = ts + TO_CLS;
    float* red = ts + TO_RED;

    const int tid = threadIdx.x;
    const int b   = blockIdx.x;

    {
        const float4* src = (const float4*)(g_xn + b * 33 * 256);
        for (int i = tid; i < 2112; i += 512) {
            int t = i >> 6, j = i & 63;
            *(float4*)(xs + t * 260 + 4 * j) = src[t * 64 + j];
        }
        const float4* rsrc = (const float4*)(g_r + b * 2048);
        if (tid < 512) ((float4*)rr)[tid] = rsrc[tid];
    }
    __syncthreads();
    {
        int i = tid >> 1, part = tid & 1;
        int h = i >> 5, t = i & 31;
        const float4* rh = (const float4*)(rr + h * 256 + part * 128);
        const float4* xt = (const float4*)(xs + t * 260 + part * 128);
        float acc = 0.f;
        #pragma unroll 8
        for (int e = 0; e < 32; e++) {
            float4 a = rh[e], c = xt[e];
            acc += a.x * c.x + a.y * c.y + a.z * c.z + a.w * c.w;
        }
        acc += __shfl_xor_sync(0xffffffffu, acc, 1);
        if (part == 0) ss[h * 34 + t] = acc * 0.17677669529663687f;
    }
    if (tid >= 496) {
        int h = (tid - 496) >> 1, part = tid & 1;
        const float4* rh = (const float4*)(rr + h * 256 + part * 128);
        const float4* xt = (const float4*)(xs + 32 * 260 + part * 128);
        float acc = 0.f;
        #pragma unroll 8
        for (int e = 0; e < 32; e++) {
            float4 a = rh[e], c = xt[e];
            acc += a.x * c.x + a.y * c.y + a.z * c.z + a.w * c.w;
        }
        acc += __shfl_xor_sync(0xffff0000u, acc, 1);
        if (part == 0) ss[h * 34 + 32] = acc * 0.17677669529663687f;
    }
    __syncthreads();
    if (tid < 256) {
        int h = tid >> 5, lane = tid & 31;
        float v = ss[h * 34 + lane];
        float v32 = (lane == 0) ? ss[h * 34 + 32] : -FLT_MAX;
        float m = fmaxf(v, v32);
        #pragma unroll
        for (int off = 16; off > 0; off >>= 1)
            m = fmaxf(m, __shfl_xor_sync(0xffffffffu, m, off));
        float e = expf(v - m);
        float e32 = (lane == 0) ? expf(ss[h * 34 + 32] - m) : 0.f;
        float s = e + e32;
        #pragma unroll
        for (int off = 16; off > 0; off >>= 1)
            s += __shfl_xor_sync(0xffffffffu, s, off);
        float inv = 1.f / s;
        ss[h * 34 + lane] = e * inv;
        if (lane == 0) ss[h * 34 + 32] = e32 * inv;
    }
    __syncthreads();
    {
        int h = tid >> 6, e4 = (tid & 63) * 4;
        float4 acc = make_float4(0.f, 0.f, 0.f, 0.f);
        #pragma unroll
        for (int t = 0; t < 33; t++) {
            float a = ss[h * 34 + t];
            float4 xv = *(const float4*)(xs + t * 260 + e4);
            acc.x += a * xv.x; acc.y += a * xv.y;
            acc.z += a * xv.z; acc.w += a * xv.w;
        }
        *(float4*)(uu + h * 256 + e4) = acc;
    }
    __syncthreads();
    {
        int d = tid >> 1, part = tid & 1;
        int h = d >> 5;
        const float4* wr = (const float4*)(wv + d * 256 + part * 128);
        const float4* up = (const float4*)(uu + h * 256 + part * 128);
        float acc = 0.f;
        #pragma unroll 8
        for (int e = 0; e < 32; e++) {
            float4 a = wr[e], c = up[e];
            acc += a.x * c.x + a.y * c.y + a.z * c.z + a.w * c.w;
        }
        acc += __shfl_xor_sync(0xffffffffu, acc, 1);
        if (part == 0) oo[d] = acc;
    }
    __syncthreads();
    {
        int r = tid >> 1, part = tid & 1;
        const float4* wr = (const float4*)(pw + r * 256 + part * 128);
        const float4* op = (const float4*)(oo + part * 128);
        float acc = 0.f;
        #pragma unroll 8
        for (int e = 0; e < 32; e++) {
            float4 a = wr[e], c = op[e];
            acc += a.x * c.x + a.y * c.y + a.z * c.z + a.w * c.w;
        }
        acc += __shfl_xor_sync(0xffffffffu, acc, 1);
        if (part == 0) cls[r] = acc + pb[r] + x[b * 33 * 256 + r];
    }
    __syncthreads();
    if (tid < 256) {
        float v = cls[tid];
        float s = v, sq = v * v;
        #pragma unroll
        for (int off = 16; off > 0; off >>= 1) {
            s  += __shfl_xor_sync(0xffffffffu, s, off);
            sq += __shfl_xor_sync(0xffffffffu, sq, off);
        }
        int wid = tid >> 5, lane = tid & 31;
        if (lane == 0) { red[wid] = s; red[8 + wid] = sq; }
    }
    __syncthreads();
    if (tid == 0) {
        float tsum = 0.f, tq = 0.f;
        for (int i = 0; i < 8; i++) { tsum += red[i]; tq += red[8 + i]; }
        float mu = tsum * (1.f / 256.f);
        red[16] = mu;
        red[17] = rsqrtf(tq * (1.f / 256.f) - mu * mu + 1e-6f);
    }
    __syncthreads();
    if (tid < 256)
        out[b * 33 * 256 + tid] = (cls[tid] - red[16]) * red[17] * cng[tid] + cnb[tid];
}

// ---------------------------------------------------------------------------
extern "C" void kernel_launch(void* const* d_in, const int* in_sizes, int n_in,
                              void* d_out, int out_size) {
    const float* x    = (const float*)d_in[0];
    const float* an_g = (const float*)d_in[1];
    const float* an_b = (const float*)d_in[2];
    const float* cn_g = (const float*)d_in[3];
    const float* cn_b = (const float*)d_in[4];
    const float* wq   = (const float*)d_in[5];
    const float* wk   = (const float*)d_in[6];
    const float* wv   = (const float*)d_in[7];
    const float* pw   = (const float*)d_in[8];
    const float* pb   = (const float*)d_in[9];
    const float* se   = (const float*)d_in[10];
    const float* sd   = (const float*)d_in[11];
    const float* s_c1w = (const float*)d_in[12];
    const float* s_c1b = (const float*)d_in[13];
    const float* s_c2w = (const float*)d_in[14];
    const float* s_c2b = (const float*)d_in[15];
    const float* s_g  = (const float*)d_in[16];
    const float* s_b  = (const float*)d_in[17];
    const float* s_m  = (const float*)d_in[18];
    const float* s_v  = (const float*)d_in[19];
    const float* te   = (const float*)d_in[20];
    const float* td   = (const float*)d_in[21];
    const float* t_c1w = (const float*)d_in[22];
    const float* t_c1b = (const float*)d_in[23];
    const float* t_c2w = (const float*)d_in[24];
    const float* t_c2b = (const float*)d_in[25];
    const float* t_g  = (const float*)d_in[26];
    const float* t_b  = (const float*)d_in[27];
    const float* t_m  = (const float*)d_in[28];
    const float* t_v  = (const float*)d_in[29];
    float* out = (float*)d_out;

    cudaFuncSetAttribute(k_morph, cudaFuncAttributeMaxDynamicSharedMemorySize, M5_TOT * 4);
    cudaFuncSetAttribute(k_conv,  cudaFuncAttributeMaxDynamicSharedMemorySize, 20752 * 4);
    cudaFuncSetAttribute(k_tail,  cudaFuncAttributeMaxDynamicSharedMemorySize, TO_TOT * 4);

    k_prep<<<11, 256>>>(se, sd, te, td,
                        s_c1w, s_c1b, s_c2w, s_c2b, s_g, s_b, s_m, s_v,
                        t_c1w, t_c1b, t_c2w, t_c2b, t_g, t_b, t_m, t_v);
    k_qcls<<<dim3(8, 64), 128>>>(x, wq, wk, an_g, an_b);
    k_morph<<<dim3(4, 64), 256, M5_TOT * 4>>>(x);
    k_conv<<<dim3(2, 64), 512, 20752 * 4>>>(an_g, an_b, out);
    k_tail<<<64, 512, TO_TOT * 4>>>(x, wv, pw, pb, cn_g, cn_b, out);
}

// round 17
// speedup vs baseline: 1.2070x; 1.2070x over previous
#include <cuda_runtime.h>
#include <math.h>
#include <float.h>

// Shapes: x (64, 33, 16, 16) f32. FM=16, CIN=32, DIM=256, HEADS=8, hd=32.

__device__ float g_morph[64 * 4 * 16 * 256];  // [b][map][o][pos]
__device__ float g_xn[64 * 33 * 256];         // LN'd tokens
__device__ float g_r[64 * 8 * 256];           // per-(b,h) projected query row
__device__ float g_wpack[2 * 576 * 16];       // conv weights, bn folded
__device__ float g_cbias[2 * 16];
__device__ float g_wmT[4 * 288 * 16];         // morph weights transposed [map][cij][o]
__device__ float g_delta[1];

// ---- f32x2 helpers ----
__device__ __forceinline__ unsigned long long f2fma(unsigned long long a, unsigned long long b,
                                                    unsigned long long c) {
    unsigned long long d;
    asm("fma.rn.f32x2 %0, %1, %2, %3;" : "=l"(d) : "l"(a), "l"(b), "l"(c));
    return d;
}
__device__ __forceinline__ unsigned long long f2dup(float x) {
    unsigned long long d;
    unsigned int u = __float_as_uint(x);
    asm("mov.b64 %0, {%1, %2};" : "=l"(d) : "r"(u), "r"(u));
    return d;
}
__device__ __forceinline__ void f2unpack(unsigned long long v, float& lo, float& hi) {
    unsigned int a, b;
    asm("mov.b64 {%0, %1}, %2;" : "=r"(a), "=r"(b) : "l"(v));
    lo = __uint_as_float(a); hi = __uint_as_float(b);
}

// ---------------------------------------------------------------------------
// Init: prep (blocks 0..10) + qcls (blocks 11..522). 256 threads.
// ---------------------------------------------------------------------------
__global__ void k_init(const float* __restrict__ x,
                       const float* __restrict__ wq, const float* __restrict__ wk,
                       const float* __restrict__ an_g, const float* __restrict__ an_b,
                       const float* __restrict__ w_se, const float* __restrict__ w_sd,
                       const float* __restrict__ w_te, const float* __restrict__ w_td,
    const float* __restrict__ s_c1w, const float* __restrict__ s_c1b,
    const float* __restrict__ s_c2w, const float* __restrict__ s_c2b,
    const float* __restrict__ s_g, const float* __restrict__ s_b,
    const float* __restrict__ s_m, const float* __restrict__ s_v,
    const float* __restrict__ t_c1w, const float* __restrict__ t_c1b,
    const float* __restrict__ t_c2w, const float* __restrict__ t_c2b,
    const float* __restrict__ t_g, const float* __restrict__ t_b,
    const float* __restrict__ t_m, const float* __restrict__ t_v)
{
    const int tid = threadIdx.x;
    const int bid = blockIdx.x;
    const float* wsrc[4] = {w_se, w_sd, w_te, w_td};

    if (bid < 8) {          // morph weight transpose
        int m = bid >> 1, half = bid & 1;
        const float* src = wsrc[m];
        for (int e = half * 2304 + tid; e < half * 2304 + 2304; e += 256) {
            int cij = e >> 4, o = e & 15;
            g_wmT[m * 4608 + e] = src[o * 288 + cij];
        }
        return;
    }
    if (bid == 8) {         // delta
        __shared__ float red8[16];
        float mx = -FLT_MAX, mn = FLT_MAX;
        for (int i = tid; i < 18432; i += 256) {
            float v = wsrc[i / 4608][i % 4608];
            mx = fmaxf(mx, v); mn = fminf(mn, v);
        }
        for (int off = 16; off > 0; off >>= 1) {
            mx = fmaxf(mx, __shfl_xor_sync(0xffffffffu, mx, off));
            mn = fminf(mn, __shfl_xor_sync(0xffffffffu, mn, off));
        }
        int wid = tid >> 5, lane = tid & 31;
        if (lane == 0) { red8[wid] = mx; red8[8 + wid] = mn; }
        __syncthreads();
        if (tid == 0) {
            float a = red8[0], c = red8[8];
            for (int i = 1; i < 8; i++) { a = fmaxf(a, red8[i]); c = fminf(c, red8[8 + i]); }
            g_delta[0] = (a - c) * 1.0001f + 1e-6f;
        }
        return;
    }
    if (bid == 9) {         // conv pack br0
        for (int i = tid; i < 512; i += 256) {
            int k = i >> 4, o = i & 15;
            int ch = k >> 1, m = k & 1;
            float bns = s_g[o] * rsqrtf(s_v[o] + 1e-5f);
            float w = (m ? s_c2w : s_c1w)[o * 16 + ch];
            g_wpack[k * 16 + o] = w * bns;
        }
        if (tid < 16) {
            float bns = s_g[tid] * rsqrtf(s_v[tid] + 1e-5f);
            g_cbias[tid] = (s_c1b[tid] + s_c2b[tid]) * bns + s_b[tid] - s_m[tid] * bns;
        }
        return;
    }
    if (bid == 10) {        // conv pack br1
        for (int i = tid; i < 9216; i += 256) {
            int k = i >> 4, o = i & 15;
            int ch = k / 18; int r = k % 18; int m = r / 9; int tap = r % 9;
            float bns = t_g[o] * rsqrtf(t_v[o] + 1e-5f);
            float w = (m ? t_c2w : t_c1w)[(o * 16 + ch) * 9 + tap];
            g_wpack[9216 + k * 16 + o] = w * bns;
        }
        if (tid < 16) {
            float bns = t_g[tid] * rsqrtf(t_v[tid] + 1e-5f);
            g_cbias[16 + tid] = (t_c1b[tid] + t_c2b[tid]) * bns + t_b[tid] - t_m[tid] * bns;
        }
        return;
    }

    // ---- qcls: bid-11 = b*8 + h; 256 threads ----
    __shared__ float xn0[256];
    __shared__ float qs[32];
    __shared__ float red[20];
    const int qb = bid - 11;
    const int b = qb >> 3, h = qb & 7;
    const int wid = tid >> 5, lane = tid & 31;

    float v = x[b * 33 * 256 + tid];
    {
        float s = v, sq = v * v;
        #pragma unroll
        for (int off = 16; off > 0; off >>= 1) {
            s  += __shfl_xor_sync(0xffffffffu, s, off);
            sq += __shfl_xor_sync(0xffffffffu, sq, off);
        }
        if (lane == 0) { red[wid] = s; red[8 + wid] = sq; }
        __syncthreads();
        if (tid == 0) {
            float ts = 0.f, tq = 0.f;
            for (int i = 0; i < 8; i++) { ts += red[i]; tq += red[8 + i]; }
            float mu = ts * (1.f / 256.f);
            red[16] = mu;
            red[17] = rsqrtf(tq * (1.f / 256.f) - mu * mu + 1e-6f);
        }
        __syncthreads();
        float a0 = (v - red[16]) * red[17] * an_g[tid] + an_b[tid];
        xn0[tid] = a0;
        if (h == 0) g_xn[b * 33 * 256 + tid] = a0;
    }
    __syncthreads();
    // q[d]: 8 threads per row (32 rows)
    {
        int d = tid >> 3, part = tid & 7;
        const float4* wr = (const float4*)(wq + (h * 32 + d) * 256 + part * 32);
        const float4* x0 = (const float4*)(xn0 + part * 32);
        float acc = 0.f;
        #pragma unroll
        for (int e = 0; e < 8; e++) {
            float4 a = wr[e], c = x0[e];
            acc += a.x * c.x + a.y * c.y + a.z * c.z + a.w * c.w;
        }
        acc += __shfl_xor_sync(0xffffffffu, acc, 1);
        acc += __shfl_xor_sync(0xffffffffu, acc, 2);
        acc += __shfl_xor_sync(0xffffffffu, acc, 4);
        if (part == 0) qs[d] = acc;
    }
    __syncthreads();
    // r[e]: one element per thread
    {
        float a0 = 0.f;
        const float* wkb = wk + (h * 32) * 256 + tid;
        #pragma unroll 8
        for (int d = 0; d < 32; d++)
            a0 += qs[d] * wkb[d * 256];
        g_r[(b * 8 + h) * 256 + tid] = a0;
    }
}

// smem float offsets for k_morph v4 (row-quarter tiles)
#define MO_X   0        // 3456
#define MO_HX  3456     // 3072
#define MO_HN  6528     // 3072
#define MO_VX  9600     // 2048
#define MO_VN  11648    // 2048
#define MO_TOT 13696

// ---------------------------------------------------------------------------
// Morphology v4 (R14, best measured class): grid (4, 64), 256 threads.
// ---------------------------------------------------------------------------
__global__ void __launch_bounds__(256, 4)
k_morph(const float* __restrict__ x)
{
    extern __shared__ float sm[];
    float* x_sm = sm + MO_X;
    float* hmx  = sm + MO_HX;
    float* hmn  = sm + MO_HN;
    float* vmx  = sm + MO_VX;
    float* vmn  = sm + MO_VN;

    const int tid = threadIdx.x;
    const int qtr = blockIdx.x;
    const int b   = blockIdx.y;
    const int hbase = qtr * 4;

    for (int i = tid; i < 3456; i += 256) {
        int c = i / 108; int rem = i % 108; int r = rem / 18; int cc = rem % 18;
        int gr = hbase - 1 + r; int gc = cc - 1;
        float v = 0.f;
        if (gr >= 0 && gr < 16 && gc >= 0 && gc < 16)
            v = x[((b * 33 + 1 + c) * 16 + gr) * 16 + gc];
        x_sm[i] = v;
    }
    __syncthreads();
    for (int i = tid; i < 3072; i += 256) {
        int c = i / 96; int rem = i - c * 96;
        int base = c * 108 + (rem >> 4) * 18 + (rem & 15);
        float v0 = x_sm[base], v1 = x_sm[base + 1], v2 = x_sm[base + 2];
        int ha = c * 96 + rem;
        hmx[ha] = fmaxf(fmaxf(v0, v1), v2);
        hmn[ha] = fminf(fminf(v0, v1), v2);
    }
    __syncthreads();
    for (int i = tid; i < 2048; i += 256) {
        int c = i >> 6; int p = i & 63;
        int base = c * 96 + (p >> 4) * 16 + (p & 15);
        vmx[i] = fmaxf(fmaxf(hmx[base], hmx[base + 16]), hmx[base + 32]);
        vmn[i] = fminf(fminf(hmn[base], hmn[base + 16]), hmn[base + 32]);
    }
    __syncthreads();

    const int pos  = tid >> 2;
    const int part = tid & 3;
    const int lh = pos >> 4;
    const int lw = pos & 15;
    const float delta = g_delta[0];
    const bool dil = (part < 2);
    const int map = dil ? (part == 0 ? 1 : 3) : (part == 2 ? 0 : 2);
    const float* vt = dil ? vmx : vmn;

    float ext = dil ? -FLT_MAX : FLT_MAX;
    if (dil) {
        #pragma unroll 8
        for (int c = 0; c < 32; c++) ext = fmaxf(ext, vt[c * 64 + pos]);
    } else {
        #pragma unroll 8
        for (int c = 0; c < 32; c++) ext = fminf(ext, vt[c * 64 + pos]);
    }
    const float thr = dil ? (ext - delta) : (ext + delta);

    unsigned msk = 0;
    if (dil) {
        #pragma unroll 8
        for (int c = 0; c < 32; c++) msk |= (vt[c * 64 + pos] >= thr ? 1u : 0u) << c;
    } else {
        #pragma unroll 8
        for (int c = 0; c < 32; c++) msk |= (vt[c * 64 + pos] <= thr ? 1u : 0u) << c;
    }

    float acc[16];
    #pragma unroll
    for (int o = 0; o < 16; o++) acc[o] = -FLT_MAX;

    const float* wT = g_wmT + map * 4608;
    while (msk) {
        int c = __ffs(msk) - 1; msk &= msk - 1;
        const float* xb = x_sm + c * 108 + lh * 18 + lw;
        #pragma unroll
        for (int ir = 0; ir < 3; ir++)
            #pragma unroll
            for (int jc = 0; jc < 3; jc++) {
                float v = xb[ir * 18 + jc];
                bool hit = dil ? (v >= thr) : (v <= thr);
                if (hit) {
                    float s = dil ? v : -v;
                    const float4* wp = (const float4*)(wT + (c * 9 + ir * 3 + jc) * 16);
                    float4 w0 = wp[0], w1 = wp[1], w2 = wp[2], w3 = wp[3];
                    acc[0]  = fmaxf(acc[0],  w0.x + s);
                    acc[1]  = fmaxf(acc[1],  w0.y + s);
                    acc[2]  = fmaxf(acc[2],  w0.z + s);
                    acc[3]  = fmaxf(acc[3],  w0.w + s);
                    acc[4]  = fmaxf(acc[4],  w1.x + s);
                    acc[5]  = fmaxf(acc[5],  w1.y + s);
                    acc[6]  = fmaxf(acc[6],  w1.z + s);
                    acc[7]  = fmaxf(acc[7],  w1.w + s);
                    acc[8]  = fmaxf(acc[8],  w2.x + s);
                    acc[9]  = fmaxf(acc[9],  w2.y + s);
                    acc[10] = fmaxf(acc[10], w2.z + s);
                    acc[11] = fmaxf(acc[11], w2.w + s);
                    acc[12] = fmaxf(acc[12], w3.x + s);
                    acc[13] = fmaxf(acc[13], w3.y + s);
                    acc[14] = fmaxf(acc[14], w3.z + s);
                    acc[15] = fmaxf(acc[15], w3.w + s);
                }
            }
    }

    const int gp = (hbase + lh) * 16 + lw;
    float* gb = g_morph + b * 16384 + map * 4096;
    const float sgn = dil ? 1.f : -1.f;
    #pragma unroll
    for (int o = 0; o < 16; o++)
        gb[o * 256 + gp] = sgn * acc[o];
}

// ---------------------------------------------------------------------------
// Conv (R14, measured 25.1us): grid (2, 64), 512 threads, fused an-LN.
// ---------------------------------------------------------------------------
__global__ void k_conv(const float* __restrict__ an_g, const float* __restrict__ an_b,
                       float* __restrict__ out)
{
    extern __shared__ float cs[];
    float* wsm = cs;              // 9216
    float* dsm = cs + 9216;       // 11520
    float* cbs = cs + 20736;      // 16
    __shared__ float psum[16][4], psq[16][4];
    __shared__ float mv[16][2];

    const int tid = threadIdx.x;
    const int br  = blockIdx.x;
    const int b   = blockIdx.y;

    {
        const float4* ws4 = (const float4*)(g_wpack + br * 9216);
        const int n4 = br ? 2304 : 128;
        for (int i = tid; i < n4; i += 512) ((float4*)wsm)[i] = ws4[i];
    }
    if (tid < 16) cbs[tid] = g_cbias[br * 16 + tid];
    for (int i = tid; i < 2880; i += 512) ((float4*)dsm)[i] = make_float4(0.f, 0.f, 0.f, 0.f);
    __syncthreads();
    {
        const float* gm = g_morph + (b * 4 + br * 2) * 4096;
        for (int i = tid; i < 8192; i += 512) {
            int m = i >> 12; int ch = (i >> 8) & 15; int p = i & 255;
            int h = p >> 4; int w = p & 15;
            dsm[(m * 16 + ch) * 360 + (h + 1) * 20 + (w + 1)] = gm[i];
        }
    }
    __syncthreads();

    const int osel4 = tid >> 7;
    const int ob0   = osel4 * 4;
    const int p2    = tid & 127;
    const int h     = p2 >> 3;
    const int w0    = (p2 & 7) * 2;

    unsigned long long acc0[2], acc1[2];
    {
        const unsigned long long* cbp = (const unsigned long long*)(cbs + ob0);
        acc0[0] = cbp[0]; acc0[1] = cbp[1];
        acc1[0] = cbp[0]; acc1[1] = cbp[1];
    }

    if (br == 0) {
        #pragma unroll 8
        for (int k = 0; k < 32; k++) {
            int ch = k >> 1, m = k & 1;
            const float* db = dsm + (m * 16 + ch) * 360 + (h + 1) * 20 + (w0 + 1);
            unsigned long long d0 = f2dup(db[0]);
            unsigned long long d1 = f2dup(db[1]);
            float4 w4 = *(const float4*)(wsm + k * 16 + ob0);
            unsigned long long wlo, whi;
            {
                unsigned int ax = __float_as_uint(w4.x), ay = __float_as_uint(w4.y);
                unsigned int az = __float_as_uint(w4.z), aw = __float_as_uint(w4.w);
                asm("mov.b64 %0, {%1, %2};" : "=l"(wlo) : "r"(ax), "r"(ay));
                asm("mov.b64 %0, {%1, %2};" : "=l"(whi) : "r"(az), "r"(aw));
            }
            acc0[0] = f2fma(wlo, d0, acc0[0]);
            acc0[1] = f2fma(whi, d0, acc0[1]);
            acc1[0] = f2fma(wlo, d1, acc1[0]);
            acc1[1] = f2fma(whi, d1, acc1[1]);
        }
    } else {
        #pragma unroll 1
        for (int ch = 0; ch < 16; ch++) {
            #pragma unroll
            for (int m = 0; m < 2; m++) {
                const float* db = dsm + (m * 16 + ch) * 360 + h * 20 + w0;
                float r0[4], r1[4], r2[4];
                {
                    float2 t;
                    t = *(const float2*)(db);          r0[0] = t.x; r0[1] = t.y;
                    t = *(const float2*)(db + 2);      r0[2] = t.x; r0[3] = t.y;
                    t = *(const float2*)(db + 20);     r1[0] = t.x; r1[1] = t.y;
                    t = *(const float2*)(db + 22);     r1[2] = t.x; r1[3] = t.y;
                    t = *(const float2*)(db + 40);     r2[0] = t.x; r2[1] = t.y;
                    t = *(const float2*)(db + 42);     r2[2] = t.x; r2[3] = t.y;
                }
                const float* wb = wsm + (ch * 18 + m * 9) * 16 + ob0;
                #pragma unroll
                for (int tap = 0; tap < 9; tap++) {
                    int ki = tap / 3, kj = tap % 3;
                    float va, vb2;
                    if (ki == 0)      { va = r0[kj]; vb2 = r0[kj + 1]; }
                    else if (ki == 1) { va = r1[kj]; vb2 = r1[kj + 1]; }
                    else              { va = r2[kj]; vb2 = r2[kj + 1]; }
                    unsigned long long d0 = f2dup(va);
                    unsigned long long d1 = f2dup(vb2);
                    float4 w4 = *(const float4*)(wb + tap * 16);
                    unsigned long long wlo, whi;
                    {
                        unsigned int ax = __float_as_uint(w4.x), ay = __float_as_uint(w4.y);
                        unsigned int az = __float_as_uint(w4.z), aw = __float_as_uint(w4.w);
                        asm("mov.b64 %0, {%1, %2};" : "=l"(wlo) : "r"(ax), "r"(ay));
                        asm("mov.b64 %0, {%1, %2};" : "=l"(whi) : "r"(az), "r"(aw));
                    }
                    acc0[0] = f2fma(wlo, d0, acc0[0]);
                    acc0[1] = f2fma(whi, d0, acc0[1]);
                    acc1[0] = f2fma(wlo, d1, acc1[0]);
                    acc1[1] = f2fma(whi, d1, acc1[1]);
                }
            }
        }
    }

    float z0[4], z1[4];
    f2unpack(acc0[0], z0[0], z0[1]);
    f2unpack(acc0[1], z0[2], z0[3]);
    f2unpack(acc1[0], z1[0], z1[1]);
    f2unpack(acc1[1], z1[2], z1[3]);

    const int pos0 = h * 16 + w0;
    const int wg   = (tid >> 5) & 3;
    const int lane = tid & 31;
    float* ob = out + (b * 33 + 1 + br * 16 + ob0) * 256;
    float g0[4], g1[4];
    #pragma unroll
    for (int ol = 0; ol < 4; ol++) {
        float a = z0[ol], c = z1[ol];
        float ga = 0.5f * a * (1.f + erff(a * 0.70710678118654752f));
        float gc = 0.5f * c * (1.f + erff(c * 0.70710678118654752f));
        g0[ol] = ga; g1[ol] = gc;
        *(float2*)(ob + ol * 256 + pos0) = make_float2(ga, gc);
        float s = ga + gc, sq = ga * ga + gc * gc;
        #pragma unroll
        for (int off = 16; off > 0; off >>= 1) {
            s  += __shfl_xor_sync(0xffffffffu, s, off);
            sq += __shfl_xor_sync(0xffffffffu, sq, off);
        }
        if (lane == 0) { psum[ob0 + ol][wg] = s; psq[ob0 + ol][wg] = sq; }
    }
    __syncthreads();
    if (tid < 16) {
        float s = psum[tid][0] + psum[tid][1] + psum[tid][2] + psum[tid][3];
        float sq = psq[tid][0] + psq[tid][1] + psq[tid][2] + psq[tid][3];
        float mu = s * (1.f / 256.f);
        float var = sq * (1.f / 256.f) - mu * mu;
        mv[tid][0] = mu;
        mv[tid][1] = rsqrtf(var + 1e-6f);
    }
    __syncthreads();
    float2 ag = *(const float2*)(an_g + pos0);
    float2 ab = *(const float2*)(an_b + pos0);
    float* xb = g_xn + (b * 33 + 1 + br * 16 + ob0) * 256;
    #pragma unroll
    for (int ol = 0; ol < 4; ol++) {
        float mu = mv[ob0 + ol][0], inv = mv[ob0 + ol][1];
        *(float2*)(xb + ol * 256 + pos0) =
            make_float2((g0[ol] - mu) * inv * ag.x + ab.x,
                        (g1[ol] - mu) * inv * ag.y + ab.y);
    }
}

// smem float offsets for k_tail
#define TO_XS  0        // 8580
#define TO_RR  8580     // 2048
#define TO_SS  10628    // 272
#define TO_UU  10900    // 2048
#define TO_OO  12948    // 256
#define TO_CLS 13204    // 256
#define TO_RED 13460    // 32
#define TO_TOT 13492

// ---------------------------------------------------------------------------
// Tail (R11, best measured): scores..cn-LN. grid 64, 512 threads.
// ---------------------------------------------------------------------------
__global__ void k_tail(const float* __restrict__ x,
                       const float* __restrict__ wv,
                       const float* __restrict__ pw, const float* __restrict__ pb,
                       const float* __restrict__ cng, const float* __restrict__ cnb,
                       float* __restrict__ out)
{
    extern __shared__ float ts[];
    float* xs  = ts + TO_XS;
    float* rr  = ts + TO_RR;
    float* ss  = ts + TO_SS;
    float* uu  = ts + TO_UU;
    float* oo  = ts + TO_OO;
    float* cls = ts + TO_CLS;
    float* red = ts + TO_RED;

    const int tid = threadIdx.x;
    const int b   = blockIdx.x;

    {
        const float4* src = (const float4*)(g_xn + b * 33 * 256);
        for (int i = tid; i < 2112; i += 512) {
            int t = i >> 6, j = i & 63;
            *(float4*)(xs + t * 260 + 4 * j) = src[t * 64 + j];
        }
        const float4* rsrc = (const float4*)(g_r + b * 2048);
        if (tid < 512) ((float4*)rr)[tid] = rsrc[tid];
    }
    __syncthreads();
    {
        int i = tid >> 1, part = tid & 1;
        int h = i >> 5, t = i & 31;
        const float4* rh = (const float4*)(rr + h * 256 + part * 128);
        const float4* xt = (const float4*)(xs + t * 260 + part * 128);
        float acc = 0.f;
        #pragma unroll 8
        for (int e = 0; e < 32; e++) {
            float4 a = rh[e], c = xt[e];
            acc += a.x * c.x + a.y * c.y + a.z * c.z + a.w * c.w;
        }
        acc += __shfl_xor_sync(0xffffffffu, acc, 1);
        if (part == 0) ss[h * 34 + t] = acc * 0.17677669529663687f;
    }
    if (tid >= 496) {
        int h = (tid - 496) >> 1, part = tid & 1;
        const float4* rh = (const float4*)(rr + h * 256 + part * 128);
        const float4* xt = (const float4*)(xs + 32 * 260 + part * 128);
        float acc = 0.f;
        #pragma unroll 8
        for (int e = 0; e < 32; e++) {
            float4 a = rh[e], c = xt[e];
            acc += a.x * c.x + a.y * c.y + a.z * c.z + a.w * c.w;
        }
        acc += __shfl_xor_sync(0xffff0000u, acc, 1);
        if (part == 0) ss[h * 34 + 32] = acc * 0.17677669529663687f;
    }
    __syncthreads();
    if (tid < 256) {
        int h = tid >> 5, lane = tid & 31;
        float v = ss[h * 34 + lane];
        float v32 = (lane == 0) ? ss[h * 34 + 32] : -FLT_MAX;
        float m = fmaxf(v, v32);
        #pragma unroll
        for (int off = 16; off > 0; off >>= 1)
            m = fmaxf(m, __shfl_xor_sync(0xffffffffu, m, off));
        float e = expf(v - m);
        float e32 = (lane == 0) ? expf(ss[h * 34 + 32] - m) : 0.f;
        float s = e + e32;
        #pragma unroll
        for (int off = 16; off > 0; off >>= 1)
            s += __shfl_xor_sync(0xffffffffu, s, off);
        float inv = 1.f / s;
        ss[h * 34 + lane] = e * inv;
        if (lane == 0) ss[h * 34 + 32] = e32 * inv;
    }
    __syncthreads();
    {
        int h = tid >> 6, e4 = (tid & 63) * 4;
        float4 acc = make_float4(0.f, 0.f, 0.f, 0.f);
        #pragma unroll
        for (int t = 0; t < 33; t++) {
            float a = ss[h * 34 + t];
            float4 xv = *(const float4*)(xs + t * 260 + e4);
            acc.x += a * xv.x; acc.y += a * xv.y;
            acc.z += a * xv.z; acc.w += a * xv.w;
        }
        *(float4*)(uu + h * 256 + e4) = acc;
    }
    __syncthreads();
    {
        int d = tid >> 1, part = tid & 1;
        int h = d >> 5;
        const float4* wr = (const float4*)(wv + d * 256 + part * 128);
        const float4* up = (const float4*)(uu + h * 256 + part * 128);
        float acc = 0.f;
        #pragma unroll 8
        for (int e = 0; e < 32; e++) {
            float4 a = wr[e], c = up[e];
            acc += a.x * c.x + a.y * c.y + a.z * c.z + a.w * c.w;
        }
        acc += __shfl_xor_sync(0xffffffffu, acc, 1);
        if (part == 0) oo[d] = acc;
    }
    __syncthreads();
    {
        int r = tid >> 1, part = tid & 1;
        const float4* wr = (const float4*)(pw + r * 256 + part * 128);
        const float4* op = (const float4*)(oo + part * 128);
        float acc = 0.f;
        #pragma unroll 8
        for (int e = 0; e < 32; e++) {
            float4 a = wr[e], c = op[e];
            acc += a.x * c.x + a.y * c.y + a.z * c.z + a.w * c.w;
        }
        acc += __shfl_xor_sync(0xffffffffu, acc, 1);
        if (part == 0) cls[r] = acc + pb[r] + x[b * 33 * 256 + r];
    }
    __syncthreads();
    if (tid < 256) {
        float v = cls[tid];
        float s = v, sq = v * v;
        #pragma unroll
        for (int off = 16; off > 0; off >>= 1) {
            s  += __shfl_xor_sync(0xffffffffu, s, off);
            sq += __shfl_xor_sync(0xffffffffu, sq, off);
        }
        int wid = tid >> 5, lane = tid & 31;
        if (lane == 0) { red[wid] = s; red[8 + wid] = sq; }
    }
    __syncthreads();
    if (tid == 0) {
        float tsum = 0.f, tq = 0.f;
        for (int i = 0; i < 8; i++) { tsum += red[i]; tq += red[8 + i]; }
        float mu = tsum * (1.f / 256.f);
        red[16] = mu;
        red[17] = rsqrtf(tq * (1.f / 256.f) - mu * mu + 1e-6f);
    }
    __syncthreads();
    if (tid < 256)
        out[b * 33 * 256 + tid] = (cls[tid] - red[16]) * red[17] * cng[tid] + cnb[tid];
}

// ---------------------------------------------------------------------------
extern "C" void kernel_launch(void* const* d_in, const int* in_sizes, int n_in,
                              void* d_out, int out_size) {
    const float* x    = (const float*)d_in[0];
    const float* an_g = (const float*)d_in[1];
    const float* an_b = (const float*)d_in[2];
    const float* cn_g = (const float*)d_in[3];
    const float* cn_b = (const float*)d_in[4];
    const float* wq   = (const float*)d_in[5];
    const float* wk   = (const float*)d_in[6];
    const float* wv   = (const float*)d_in[7];
    const float* pw   = (const float*)d_in[8];
    const float* pb   = (const float*)d_in[9];
    const float* se   = (const float*)d_in[10];
    const float* sd   = (const float*)d_in[11];
    const float* s_c1w = (const float*)d_in[12];
    const float* s_c1b = (const float*)d_in[13];
    const float* s_c2w = (const float*)d_in[14];
    const float* s_c2b = (const float*)d_in[15];
    const float* s_g  = (const float*)d_in[16];
    const float* s_b  = (const float*)d_in[17];
    const float* s_m  = (const float*)d_in[18];
    const float* s_v  = (const float*)d_in[19];
    const float* te   = (const float*)d_in[20];
    const float* td   = (const float*)d_in[21];
    const float* t_c1w = (const float*)d_in[22];
    const float* t_c1b = (const float*)d_in[23];
    const float* t_c2w = (const float*)d_in[24];
    const float* t_c2b = (const float*)d_in[25];
    const float* t_g  = (const float*)d_in[26];
    const float* t_b  = (const float*)d_in[27];
    const float* t_m  = (const float*)d_in[28];
    const float* t_v  = (const float*)d_in[29];
    float* out = (float*)d_out;

    cudaFuncSetAttribute(k_morph, cudaFuncAttributeMaxDynamicSharedMemorySize, MO_TOT * 4);
    cudaFuncSetAttribute(k_conv,  cudaFuncAttributeMaxDynamicSharedMemorySize, 20752 * 4);
    cudaFuncSetAttribute(k_tail,  cudaFuncAttributeMaxDynamicSharedMemorySize, TO_TOT * 4);

    k_init<<<523, 256>>>(x, wq, wk, an_g, an_b, se, sd, te, td,
                         s_c1w, s_c1b, s_c2w, s_c2b, s_g, s_b, s_m, s_v,
                         t_c1w, t_c1b, t_c2w, t_c2b, t_g, t_b, t_m, t_v);
    k_morph<<<dim3(4, 64), 256, MO_TOT * 4>>>(x);
    k_conv<<<dim3(2, 64), 512, 20752 * 4>>>(an_g, an_b, out);
    k_tail<<<64, 512, TO_TOT * 4>>>(x, wv, pw, pb, cn_g, cn_b, out);
}